// round 10
// baseline (speedup 1.0000x reference)
#include <cuda_runtime.h>
#include <cuda_fp16.h>
#include <math.h>
#include <stdint.h>

#define N_NODES 8192
#define IN_F    512
#define OUT_F   64

__device__ float  d_h[N_NODES * OUT_F];
__device__ float  d_r[N_NODES];
__device__ float  d_pmax[128];
__device__ __half d_HpTc[128 * 72 * 72];       // chunk-major: [chunk][n 0..71][pos 0..63 (+pad)]
__device__ float  d_part[2 * N_NODES * 80];

// ---------------------------------------------------------------------------
// helpers
// ---------------------------------------------------------------------------
__device__ __forceinline__ void mma16816(float* c,
    uint32_t a0, uint32_t a1, uint32_t a2, uint32_t a3,
    uint32_t b0, uint32_t b1) {
    asm volatile(
        "mma.sync.aligned.m16n8k16.row.col.f32.f16.f16.f32 "
        "{%0,%1,%2,%3},{%4,%5,%6,%7},{%8,%9},{%0,%1,%2,%3};\n"
        : "+f"(c[0]), "+f"(c[1]), "+f"(c[2]), "+f"(c[3])
        : "r"(a0), "r"(a1), "r"(a2), "r"(a3), "r"(b0), "r"(b1));
}

__device__ __forceinline__ void ldsm_x4(uint32_t& r0, uint32_t& r1,
                                        uint32_t& r2, uint32_t& r3, uint32_t addr) {
    asm volatile("ldmatrix.sync.aligned.m8n8.x4.shared.b16 {%0,%1,%2,%3}, [%4];\n"
        : "=r"(r0), "=r"(r1), "=r"(r2), "=r"(r3) : "r"(addr));
}
__device__ __forceinline__ void ldsm_x2(uint32_t& r0, uint32_t& r1, uint32_t addr) {
    asm volatile("ldmatrix.sync.aligned.m8n8.x2.shared.b16 {%0,%1}, [%2];\n"
        : "=r"(r0), "=r"(r1) : "r"(addr));
}

__device__ __forceinline__ void cpa16(void* dst, const void* src) {
    uint32_t d = (uint32_t)__cvta_generic_to_shared(dst);
    asm volatile("cp.async.cg.shared.global [%0], [%1], 16;\n" :: "r"(d), "l"(src));
}
#define CP_COMMIT() asm volatile("cp.async.commit_group;\n" ::: "memory")
#define CP_WAIT(n)  asm volatile("cp.async.wait_group %0;\n" :: "n"(n) : "memory")

// --- TMA bulk + mbarrier ---
__device__ __forceinline__ void mbar_init(uint32_t addr, uint32_t cnt) {
    asm volatile("mbarrier.init.shared.b64 [%0], %1;" :: "r"(addr), "r"(cnt) : "memory");
}
__device__ __forceinline__ void mbar_expect_tx(uint32_t addr, uint32_t tx) {
    asm volatile("mbarrier.arrive.expect_tx.shared.b64 _, [%0], %1;"
                 :: "r"(addr), "r"(tx) : "memory");
}
__device__ __forceinline__ void mbar_wait(uint32_t addr, uint32_t parity) {
    asm volatile(
        "{\n\t.reg .pred P;\n\t"
        "LW%=:\n\t"
        "mbarrier.try_wait.parity.acquire.cta.shared::cta.b64 P, [%0], %1;\n\t"
        "@P bra LD%=;\n\t"
        "bra LW%=;\n\t"
        "LD%=:\n\t}"
        :: "r"(addr), "r"(parity) : "memory");
}
__device__ __forceinline__ void bulk_g2s(uint32_t dst, const void* src,
                                         uint32_t bytes, uint32_t mbar) {
    asm volatile(
        "cp.async.bulk.shared::cluster.global.mbarrier::complete_tx::bytes "
        "[%0], [%1], %2, [%3];"
        :: "r"(dst), "l"(src), "r"(bytes), "r"(mbar) : "memory");
}

__device__ __forceinline__ float elu1(float x) {
    return x > 0.f ? x : expm1f(x);
}

// ---------------------------------------------------------------------------
// K1: h = X @ W via fp16 mma; fused r = h.a_right, per-CTA max -> d_pmax.
// (R6 version — measured 15.4us)
// ---------------------------------------------------------------------------
#define K1_XS   (3 * 64 * 68)
#define K1_SMEM (K1_XS * 4 + 64 * 520 * 2)

__global__ void __launch_bounds__(128)
k1_mma(const float* __restrict__ X, const float* __restrict__ W,
       const float* __restrict__ avec) {
    extern __shared__ char sm1[];
    float*  Xs = (float*)sm1;
    __half* Wt = (__half*)(sm1 + K1_XS * 4);
    __shared__ float ar_s[64];
    __shared__ float wmax[4];

    const int tid  = threadIdx.x;
    const int warp = tid >> 5;
    const int lane = tid & 31;
    const int g    = lane >> 2;
    const int t    = lane & 3;
    const int row0 = blockIdx.x * 64;

    if (tid < 64) ar_s[tid] = avec[OUT_F + tid];

    for (int i = 0; i < 64; ++i) {
        int idx = i * 128 + tid;
        int k = idx >> 4, n = (idx & 15) * 4;
        float4 f = ((const float4*)W)[idx];
        Wt[(n + 0) * 520 + k] = __float2half(f.x);
        Wt[(n + 1) * 520 + k] = __float2half(f.y);
        Wt[(n + 2) * 520 + k] = __float2half(f.z);
        Wt[(n + 3) * 520 + k] = __float2half(f.w);
    }

    auto issueX = [&](int c) {
        int kc = c * 64;
        float* Xd = Xs + (c % 3) * 64 * 68;
#pragma unroll
        for (int q = 0; q < 8; ++q) {
            int idx = q * 128 + tid;
            int rr = idx >> 4, c4 = idx & 15;
            cpa16(Xd + rr * 68 + c4 * 4,
                  X + (size_t)(row0 + rr) * IN_F + kc + c4 * 4);
        }
    };
    issueX(0); CP_COMMIT();
    issueX(1); CP_COMMIT();

    float acc[8][4];
#pragma unroll
    for (int n = 0; n < 8; ++n)
#pragma unroll
        for (int i = 0; i < 4; ++i) acc[n][i] = 0.f;

    const int rb = warp * 16;
    for (int c = 0; c < 8; ++c) {
        CP_WAIT(1);
        __syncthreads();
        if (c + 2 < 8) issueX(c + 2);
        CP_COMMIT();

        const float* Xst = Xs + (c % 3) * 64 * 68;
#pragma unroll
        for (int ks = 0; ks < 4; ++ks) {
            int kk = ks * 16 + 2 * t;
            float2 f;
            __half2 h2;
            f = *(const float2*)&Xst[(rb + g) * 68 + kk];
            h2 = __float22half2_rn(f); uint32_t a0 = *(uint32_t*)&h2;
            f = *(const float2*)&Xst[(rb + g + 8) * 68 + kk];
            h2 = __float22half2_rn(f); uint32_t a1 = *(uint32_t*)&h2;
            f = *(const float2*)&Xst[(rb + g) * 68 + kk + 8];
            h2 = __float22half2_rn(f); uint32_t a2 = *(uint32_t*)&h2;
            f = *(const float2*)&Xst[(rb + g + 8) * 68 + kk + 8];
            h2 = __float22half2_rn(f); uint32_t a3 = *(uint32_t*)&h2;

            int kg = c * 64 + kk;
#pragma unroll
            for (int nt = 0; nt < 8; ++nt) {
                int n = nt * 8 + g;
                uint32_t b0 = *(const uint32_t*)&Wt[n * 520 + kg];
                uint32_t b1 = *(const uint32_t*)&Wt[n * 520 + kg + 8];
                mma16816(acc[nt], a0, a1, a2, a3, b0, b1);
            }
        }
    }

    const int rlo = row0 + rb + g;
    const int rhi = rlo + 8;
    float rlo_p = 0.f, rhi_p = 0.f;
#pragma unroll
    for (int nt = 0; nt < 8; ++nt) {
        int c0 = nt * 8 + 2 * t;
        *(float2*)&d_h[(size_t)rlo * OUT_F + c0] = make_float2(acc[nt][0], acc[nt][1]);
        *(float2*)&d_h[(size_t)rhi * OUT_F + c0] = make_float2(acc[nt][2], acc[nt][3]);
        rlo_p += acc[nt][0] * ar_s[c0] + acc[nt][1] * ar_s[c0 + 1];
        rhi_p += acc[nt][2] * ar_s[c0] + acc[nt][3] * ar_s[c0 + 1];
    }
    const unsigned full = 0xffffffffu;
    rlo_p += __shfl_xor_sync(full, rlo_p, 1);
    rlo_p += __shfl_xor_sync(full, rlo_p, 2);
    rhi_p += __shfl_xor_sync(full, rhi_p, 1);
    rhi_p += __shfl_xor_sync(full, rhi_p, 2);
    if (t == 0) {
        d_r[rlo] = rlo_p;
        d_r[rhi] = rhi_p;
    }
    float m = (t == 0) ? fmaxf(rlo_p, rhi_p) : -3.4e38f;
#pragma unroll
    for (int off = 16; off > 0; off >>= 1)
        m = fmaxf(m, __shfl_xor_sync(full, m, off));
    if (lane == 0) wmax[warp] = m;
    __syncthreads();
    if (tid == 0)
        d_pmax[blockIdx.x] = fmaxf(fmaxf(wmax[0], wmax[1]), fmaxf(wmax[2], wmax[3]));
}

// ---------------------------------------------------------------------------
// K3: w_j = exp(r_j - m); build chunk-major HpTc[cg][n][pos] (fp16):
//     n<64: w*h; n==64: w; 65..71: 0. pos pad cols 64..71 never read.
// ---------------------------------------------------------------------------
__global__ void k3_build() {
    __shared__ float hs[128][65];
    __shared__ float red[128];
    const int tid = threadIdx.x;
    const int j0  = blockIdx.x * 128;

    red[tid] = d_pmax[tid];
    __syncthreads();
    for (int st = 64; st > 0; st >>= 1) {
        if (tid < st) red[tid] = fmaxf(red[tid], red[tid + st]);
        __syncthreads();
    }
    const float smax = red[0];

#pragma unroll
    for (int it = 0; it < 64; ++it) {
        int idx = it * 128 + tid;
        int rr = idx >> 6, cc = idx & 63;
        hs[rr][cc] = d_h[(size_t)(j0 + rr) * OUT_F + cc];
    }
    __syncthreads();
    const int j  = j0 + tid;
    const int cg = j >> 6;         // chunk index
    const int p  = j & 63;         // position within chunk
    float w = expf(d_r[j] - smax);
    __half* base = d_HpTc + (size_t)cg * (72 * 72) + p;
#pragma unroll
    for (int c = 0; c < 72; ++c) {
        float v = (c < 64) ? w * hs[tid][c] : ((c == 64) ? w : 0.f);
        base[c * 72] = __float2half(v);
    }
}

// ---------------------------------------------------------------------------
// K4: K-split-2 partial GEMM, loads via cp.async.bulk (TMA) + mbarrier.
// 256 CTAs = (rowBlk 0..127) x (half 0..1). 256 threads (8 warps = rg4 x ng2).
// 4-stage ring, prefetch distance 3. A: 64x256B bulk copies (threads 0..63);
// B: ONE 10368B bulk copy (thread 64). Fragment-time int->fp16 conversion.
// smem 111136 B -> 2 CTAs/SM.
// ---------------------------------------------------------------------------
#define NSTG    4
#define A_INTS  (64 * 68)                       // ints per stage (272B rows)
#define ABYTES  (A_INTS * 4)                    // 17408
#define B_HLV   (72 * 72)                       // halves per stage
#define BBYTES  (B_HLV * 2)                     // 10368
#define OFF_B   (NSTG * ABYTES)                 // 69632
#define OFF_MB  (OFF_B + NSTG * BBYTES)         // 111104
#define K4_SMEM (OFF_MB + NSTG * 8)             // 111136
#define TXBYTES (64 * 256 + BBYTES)             // 26752

__global__ void __launch_bounds__(256, 2)
k4_split(const int* __restrict__ adj) {
    extern __shared__ char sm4[];
    int*    AIsm = (int*)sm4;                          // [4][64][68] int32
    __half* Bsm  = (__half*)(sm4 + OFF_B);             // [4][72][72] fp16

    const uint32_t smem0 = (uint32_t)__cvta_generic_to_shared(sm4);
    const uint32_t MB0   = smem0 + OFF_MB;
    const uint32_t B0    = smem0 + OFF_B;

    const int tid  = threadIdx.x;
    const int warp = tid >> 5;
    const int lane = tid & 31;
    const int t    = lane & 3;
    const int g    = lane >> 2;
    const int rg   = warp >> 1;
    const int ng   = warp & 1;
    const int rowBlk = blockIdx.x >> 1;
    const int half   = blockIdx.x & 1;
    const int row0   = rowBlk * 64;
    const int kInt0  = half * 4096;          // int32 offset into each adj row
    const int cg0    = half * 64;            // global chunk index base

    const int baseT = ng * 5;
    const int cntT  = ng ? 4 : 5;

    const int quad = lane >> 3;
    const int qr   = lane & 7;
    const int rb   = rg * 16;
    const int r0l  = rb + g;
    uint32_t boffp[2];
#pragma unroll
    for (int p = 0; p < 2; ++p) {
        int n0 = (baseT + 2 * p) * 8;
        boffp[p] = (uint32_t)((n0 + (quad >> 1) * 8 + qr) * (72 * 2)
                              + (quad & 1) * 16);
    }
    const uint32_t boffs = (uint32_t)(((baseT + 4) * 8 + qr) * (72 * 2)
                                      + (quad & 1) * 16);

    // init mbarriers (arrive count 1: the expect_tx poster)
    if (tid < NSTG) mbar_init(MB0 + tid * 8, 1);
    __syncthreads();

    auto issue = [&](int c) {
        const int st = c & 3;
        const uint32_t mb = MB0 + st * 8;
        if (tid == 0) mbar_expect_tx(mb, TXBYTES);
        if (tid < 64) {
            // one 256B row copy per thread
            const int* src = adj + (size_t)(row0 + tid) * N_NODES + kInt0 + c * 64;
            uint32_t dst = smem0 + st * ABYTES + tid * 272;
            bulk_g2s(dst, src, 256, mb);
        } else if (tid == 64) {
            const __half* src = d_HpTc + (size_t)(cg0 + c) * B_HLV;
            bulk_g2s(B0 + st * BBYTES, src, BBYTES, mb);
        }
    };

    issue(0);
    issue(1);
    issue(2);

    float acc[5][4];
#pragma unroll
    for (int n = 0; n < 5; ++n)
#pragma unroll
        for (int i = 0; i < 4; ++i) acc[n][i] = 0.f;

    for (int c = 0; c < 64; ++c) {
        const int st = c & 3;
        mbar_wait(MB0 + st * 8, (c >> 2) & 1);   // chunk c landed (acquire)

        const int*    Ast = AIsm + st * A_INTS;
        const uint32_t Bb = B0 + st * BBYTES;

#pragma unroll
        for (int ks = 0; ks < 4; ++ks) {
            int kk = ks * 16 + 2 * t;
            int2 v;
            v = *(const int2*)&Ast[r0l * 68 + kk];
            uint32_t a0 = (v.x ? 0x3C00u : 0u) | (v.y ? 0x3C000000u : 0u);
            v = *(const int2*)&Ast[(r0l + 8) * 68 + kk];
            uint32_t a1 = (v.x ? 0x3C00u : 0u) | (v.y ? 0x3C000000u : 0u);
            v = *(const int2*)&Ast[r0l * 68 + kk + 8];
            uint32_t a2 = (v.x ? 0x3C00u : 0u) | (v.y ? 0x3C000000u : 0u);
            v = *(const int2*)&Ast[(r0l + 8) * 68 + kk + 8];
            uint32_t a3 = (v.x ? 0x3C00u : 0u) | (v.y ? 0x3C000000u : 0u);

            uint32_t b[10];
            ldsm_x4(b[0], b[1], b[2], b[3], Bb + boffp[0] + ks * 32);
            ldsm_x4(b[4], b[5], b[6], b[7], Bb + boffp[1] + ks * 32);
            if (ng == 0) ldsm_x2(b[8], b[9], Bb + boffs + ks * 32);
            mma16816(acc[0], a0, a1, a2, a3, b[0], b[1]);
            mma16816(acc[1], a0, a1, a2, a3, b[2], b[3]);
            mma16816(acc[2], a0, a1, a2, a3, b[4], b[5]);
            mma16816(acc[3], a0, a1, a2, a3, b[6], b[7]);
            if (ng == 0) mma16816(acc[4], a0, a1, a2, a3, b[8], b[9]);
        }

        __syncthreads();                    // all warps done reading stage st
        if (c + 3 < 64) issue(c + 3);       // refill the just-freed stage
    }

    // store raw partials (cols: ng0 -> tiles 0..4, ng1 -> tiles 5..8 incl den 64)
    float* P = d_part + (size_t)half * N_NODES * 80;
    const int rlo = row0 + r0l;
    const int rhi = rlo + 8;
#pragma unroll
    for (int nt = 0; nt < 5; ++nt) {
        if (nt >= cntT) break;
        int gt = baseT + nt;
        int c0 = gt * 8 + 2 * t;
        *(float2*)&P[(size_t)rlo * 80 + c0] = make_float2(acc[nt][0], acc[nt][1]);
        *(float2*)&P[(size_t)rhi * 80 + c0] = make_float2(acc[nt][2], acc[nt][3]);
    }
}

// ---------------------------------------------------------------------------
// K5: combine halves: out = elu((num0+num1)/(den0+den1))
// ---------------------------------------------------------------------------
__global__ void __launch_bounds__(256)
k5_combine(float* __restrict__ out) {
    const int idx = blockIdx.x * 256 + threadIdx.x;
    const int row = idx >> 4;
    const int c0  = (idx & 15) * 4;
    const float* P0 = d_part + (size_t)row * 80;
    const float* P1 = d_part + (size_t)N_NODES * 80 + (size_t)row * 80;
    float4 n0 = *(const float4*)&P0[c0];
    float4 n1 = *(const float4*)&P1[c0];
    float den = P0[64] + P1[64];
    float inv = 1.f / den;
    float4 o;
    o.x = elu1((n0.x + n1.x) * inv);
    o.y = elu1((n0.y + n1.y) * inv);
    o.z = elu1((n0.z + n1.z) * inv);
    o.w = elu1((n0.w + n1.w) * inv);
    *(float4*)&out[(size_t)row * OUT_F + c0] = o;
}

// ---------------------------------------------------------------------------
extern "C" void kernel_launch(void* const* d_in, const int* in_sizes, int n_in,
                              void* d_out, int out_size) {
    const float* X    = (const float*)d_in[0];
    const int*   adj  = (const int*)  d_in[1];
    const float* W    = (const float*)d_in[2];
    const float* avec = (const float*)d_in[3];
    float* out = (float*)d_out;

    cudaFuncSetAttribute(k1_mma, cudaFuncAttributeMaxDynamicSharedMemorySize, K1_SMEM);
    cudaFuncSetAttribute(k4_split, cudaFuncAttributeMaxDynamicSharedMemorySize, K4_SMEM);

    k1_mma<<<128, 128, K1_SMEM>>>(X, W, avec);
    k3_build<<<64, 128>>>();
    k4_split<<<256, 256, K4_SMEM>>>(adj);
    k5_combine<<<N_NODES * OUT_F / 1024, 256>>>(out);
}

// round 11
// speedup vs baseline: 1.3631x; 1.3631x over previous
#include <cuda_runtime.h>
#include <cuda.h>
#include <cuda_fp16.h>
#include <math.h>
#include <stdint.h>

#define N_NODES 8192
#define IN_F    512
#define OUT_F   64

__device__ float  d_h[N_NODES * OUT_F];
__device__ float  d_r[N_NODES];
__device__ float  d_pmax[128];
__device__ __half d_HpTc[128 * 72 * 72];       // chunk-major: [chunk][n 0..71][pos 0..63(+pad)]
__device__ float  d_part[2 * N_NODES * 80];

// ---------------------------------------------------------------------------
// helpers
// ---------------------------------------------------------------------------
__device__ __forceinline__ void mma16816(float* c,
    uint32_t a0, uint32_t a1, uint32_t a2, uint32_t a3,
    uint32_t b0, uint32_t b1) {
    asm volatile(
        "mma.sync.aligned.m16n8k16.row.col.f32.f16.f16.f32 "
        "{%0,%1,%2,%3},{%4,%5,%6,%7},{%8,%9},{%0,%1,%2,%3};\n"
        : "+f"(c[0]), "+f"(c[1]), "+f"(c[2]), "+f"(c[3])
        : "r"(a0), "r"(a1), "r"(a2), "r"(a3), "r"(b0), "r"(b1));
}

__device__ __forceinline__ void ldsm_x4(uint32_t& r0, uint32_t& r1,
                                        uint32_t& r2, uint32_t& r3, uint32_t addr) {
    asm volatile("ldmatrix.sync.aligned.m8n8.x4.shared.b16 {%0,%1,%2,%3}, [%4];\n"
        : "=r"(r0), "=r"(r1), "=r"(r2), "=r"(r3) : "r"(addr));
}
__device__ __forceinline__ void ldsm_x2(uint32_t& r0, uint32_t& r1, uint32_t addr) {
    asm volatile("ldmatrix.sync.aligned.m8n8.x2.shared.b16 {%0,%1}, [%2];\n"
        : "=r"(r0), "=r"(r1) : "r"(addr));
}

__device__ __forceinline__ void cpa16(void* dst, const void* src) {
    uint32_t d = (uint32_t)__cvta_generic_to_shared(dst);
    asm volatile("cp.async.cg.shared.global [%0], [%1], 16;\n" :: "r"(d), "l"(src));
}
#define CP_COMMIT() asm volatile("cp.async.commit_group;\n" ::: "memory")
#define CP_WAIT(n)  asm volatile("cp.async.wait_group %0;\n" :: "n"(n) : "memory")

// --- TMA + mbarrier ---
__device__ __forceinline__ void mbar_init(uint32_t addr, uint32_t cnt) {
    asm volatile("mbarrier.init.shared.b64 [%0], %1;" :: "r"(addr), "r"(cnt) : "memory");
}
__device__ __forceinline__ void mbar_expect_tx(uint32_t addr, uint32_t tx) {
    asm volatile("mbarrier.arrive.expect_tx.shared.b64 _, [%0], %1;"
                 :: "r"(addr), "r"(tx) : "memory");
}
__device__ __forceinline__ void mbar_wait(uint32_t addr, uint32_t parity) {
    asm volatile(
        "{\n\t.reg .pred P;\n\t"
        "LW%=:\n\t"
        "mbarrier.try_wait.parity.acquire.cta.shared::cta.b64 P, [%0], %1;\n\t"
        "@P bra LD%=;\n\t"
        "bra LW%=;\n\t"
        "LD%=:\n\t}"
        :: "r"(addr), "r"(parity) : "memory");
}
__device__ __forceinline__ void bulk_g2s(uint32_t dst, const void* src,
                                         uint32_t bytes, uint32_t mbar) {
    asm volatile(
        "cp.async.bulk.shared::cluster.global.mbarrier::complete_tx::bytes "
        "[%0], [%1], %2, [%3];"
        :: "r"(dst), "l"(src), "r"(bytes), "r"(mbar) : "memory");
}
__device__ __forceinline__ void tma_2d(uint32_t dst, const void* tmap,
                                       int x, int y, uint32_t mbar) {
    asm volatile(
        "cp.async.bulk.tensor.2d.shared::cta.global.tile.mbarrier::complete_tx::bytes "
        "[%0], [%1, {%2, %3}], [%4];"
        :: "r"(dst), "l"(tmap), "r"(x), "r"(y), "r"(mbar) : "memory");
}

__device__ __forceinline__ float elu1(float x) {
    return x > 0.f ? x : expm1f(x);
}

// ---------------------------------------------------------------------------
// K1: h = X @ W via fp16 mma; fused r = h.a_right, per-CTA max -> d_pmax.
// (measured 15.4us)
// ---------------------------------------------------------------------------
#define K1_XS   (3 * 64 * 68)
#define K1_SMEM (K1_XS * 4 + 64 * 520 * 2)

__global__ void __launch_bounds__(128)
k1_mma(const float* __restrict__ X, const float* __restrict__ W,
       const float* __restrict__ avec) {
    extern __shared__ char sm1[];
    float*  Xs = (float*)sm1;
    __half* Wt = (__half*)(sm1 + K1_XS * 4);
    __shared__ float ar_s[64];
    __shared__ float wmax[4];

    const int tid  = threadIdx.x;
    const int warp = tid >> 5;
    const int lane = tid & 31;
    const int g    = lane >> 2;
    const int t    = lane & 3;
    const int row0 = blockIdx.x * 64;

    if (tid < 64) ar_s[tid] = avec[OUT_F + tid];

    for (int i = 0; i < 64; ++i) {
        int idx = i * 128 + tid;
        int k = idx >> 4, n = (idx & 15) * 4;
        float4 f = ((const float4*)W)[idx];
        Wt[(n + 0) * 520 + k] = __float2half(f.x);
        Wt[(n + 1) * 520 + k] = __float2half(f.y);
        Wt[(n + 2) * 520 + k] = __float2half(f.z);
        Wt[(n + 3) * 520 + k] = __float2half(f.w);
    }

    auto issueX = [&](int c) {
        int kc = c * 64;
        float* Xd = Xs + (c % 3) * 64 * 68;
#pragma unroll
        for (int q = 0; q < 8; ++q) {
            int idx = q * 128 + tid;
            int rr = idx >> 4, c4 = idx & 15;
            cpa16(Xd + rr * 68 + c4 * 4,
                  X + (size_t)(row0 + rr) * IN_F + kc + c4 * 4);
        }
    };
    issueX(0); CP_COMMIT();
    issueX(1); CP_COMMIT();

    float acc[8][4];
#pragma unroll
    for (int n = 0; n < 8; ++n)
#pragma unroll
        for (int i = 0; i < 4; ++i) acc[n][i] = 0.f;

    const int rb = warp * 16;
    for (int c = 0; c < 8; ++c) {
        CP_WAIT(1);
        __syncthreads();
        if (c + 2 < 8) issueX(c + 2);
        CP_COMMIT();

        const float* Xst = Xs + (c % 3) * 64 * 68;
#pragma unroll
        for (int ks = 0; ks < 4; ++ks) {
            int kk = ks * 16 + 2 * t;
            float2 f;
            __half2 h2;
            f = *(const float2*)&Xst[(rb + g) * 68 + kk];
            h2 = __float22half2_rn(f); uint32_t a0 = *(uint32_t*)&h2;
            f = *(const float2*)&Xst[(rb + g + 8) * 68 + kk];
            h2 = __float22half2_rn(f); uint32_t a1 = *(uint32_t*)&h2;
            f = *(const float2*)&Xst[(rb + g) * 68 + kk + 8];
            h2 = __float22half2_rn(f); uint32_t a2 = *(uint32_t*)&h2;
            f = *(const float2*)&Xst[(rb + g + 8) * 68 + kk + 8];
            h2 = __float22half2_rn(f); uint32_t a3 = *(uint32_t*)&h2;

            int kg = c * 64 + kk;
#pragma unroll
            for (int nt = 0; nt < 8; ++nt) {
                int n = nt * 8 + g;
                uint32_t b0 = *(const uint32_t*)&Wt[n * 520 + kg];
                uint32_t b1 = *(const uint32_t*)&Wt[n * 520 + kg + 8];
                mma16816(acc[nt], a0, a1, a2, a3, b0, b1);
            }
        }
    }

    const int rlo = row0 + rb + g;
    const int rhi = rlo + 8;
    float rlo_p = 0.f, rhi_p = 0.f;
#pragma unroll
    for (int nt = 0; nt < 8; ++nt) {
        int c0 = nt * 8 + 2 * t;
        *(float2*)&d_h[(size_t)rlo * OUT_F + c0] = make_float2(acc[nt][0], acc[nt][1]);
        *(float2*)&d_h[(size_t)rhi * OUT_F + c0] = make_float2(acc[nt][2], acc[nt][3]);
        rlo_p += acc[nt][0] * ar_s[c0] + acc[nt][1] * ar_s[c0 + 1];
        rhi_p += acc[nt][2] * ar_s[c0] + acc[nt][3] * ar_s[c0 + 1];
    }
    const unsigned full = 0xffffffffu;
    rlo_p += __shfl_xor_sync(full, rlo_p, 1);
    rlo_p += __shfl_xor_sync(full, rlo_p, 2);
    rhi_p += __shfl_xor_sync(full, rhi_p, 1);
    rhi_p += __shfl_xor_sync(full, rhi_p, 2);
    if (t == 0) {
        d_r[rlo] = rlo_p;
        d_r[rhi] = rhi_p;
    }
    float m = (t == 0) ? fmaxf(rlo_p, rhi_p) : -3.4e38f;
#pragma unroll
    for (int off = 16; off > 0; off >>= 1)
        m = fmaxf(m, __shfl_xor_sync(full, m, off));
    if (lane == 0) wmax[warp] = m;
    __syncthreads();
    if (tid == 0)
        d_pmax[blockIdx.x] = fmaxf(fmaxf(wmax[0], wmax[1]), fmaxf(wmax[2], wmax[3]));
}

// ---------------------------------------------------------------------------
// K3: w_j = exp(r_j - m); build chunk-major HpTc[cg][n][pos] (fp16).
// ---------------------------------------------------------------------------
__global__ void k3_build() {
    __shared__ float hs[128][65];
    __shared__ float red[128];
    const int tid = threadIdx.x;
    const int j0  = blockIdx.x * 128;

    red[tid] = d_pmax[tid];
    __syncthreads();
    for (int st = 64; st > 0; st >>= 1) {
        if (tid < st) red[tid] = fmaxf(red[tid], red[tid + st]);
        __syncthreads();
    }
    const float smax = red[0];

#pragma unroll
    for (int it = 0; it < 64; ++it) {
        int idx = it * 128 + tid;
        int rr = idx >> 6, cc = idx & 63;
        hs[rr][cc] = d_h[(size_t)(j0 + rr) * OUT_F + cc];
    }
    __syncthreads();
    const int j  = j0 + tid;
    const int cg = j >> 6;         // chunk index
    const int p  = j & 63;         // position within chunk
    float w = expf(d_r[j] - smax);
    __half* base = d_HpTc + (size_t)cg * (72 * 72) + p;
#pragma unroll
    for (int c = 0; c < 72; ++c) {
        float v = (c < 64) ? w * hs[tid][c] : ((c == 64) ? w : 0.f);
        base[c * 72] = __float2half(v);
    }
}

// ---------------------------------------------------------------------------
// K4: K-split-2 GEMM, A via ONE tensor-map UTMALDG per chunk (64x64 int box),
// B via ONE bulk copy per chunk. convA pass -> padded fp16 double buffer;
// ldmatrix fragments (R6-proven). 3-stage ring, prefetch 2, 2 CTAs/SM.
// ---------------------------------------------------------------------------
#define NSTG    3
#define A_INTS  (64 * 64)                       // ints per TMA stage (linear box)
#define ABYTES  (A_INTS * 4)                    // 16384
#define AF_HLV  (64 * 72)                       // fp16 buffer halves
#define B_HLV   (72 * 72)
#define BBYTES  (B_HLV * 2)                     // 10368
#define OFF_AF  (NSTG * ABYTES)                 // 49152
#define OFF_B   (OFF_AF + 2 * AF_HLV * 2)       // 67584
#define OFF_MB  (OFF_B + NSTG * BBYTES)         // 98688
#define K4_SMEM (OFF_MB + 64)                   // 98752
#define TXBYTES (ABYTES + BBYTES)               // 26752

__global__ void __launch_bounds__(256, 2)
k4_split(const __grid_constant__ CUtensorMap tmapA) {
    extern __shared__ char sm4[];
    int*    AIsm = (int*)sm4;                          // [3][64][64] int32
    __half* Afp  = (__half*)(sm4 + OFF_AF);            // [2][64][72] fp16
    __half* Bsm  = (__half*)(sm4 + OFF_B);             // [3][72][72] fp16

    const uint32_t smem0 = (uint32_t)__cvta_generic_to_shared(sm4);
    const uint32_t MB0   = smem0 + OFF_MB;
    const uint32_t A0    = smem0 + OFF_AF;
    const uint32_t B0    = smem0 + OFF_B;

    const int tid  = threadIdx.x;
    const int warp = tid >> 5;
    const int lane = tid & 31;
    const int t    = lane & 3;
    const int g    = lane >> 2;
    const int rg   = warp >> 1;
    const int ng   = warp & 1;
    const int rowBlk = blockIdx.x >> 1;
    const int half   = blockIdx.x & 1;
    const int row0   = rowBlk * 64;
    const int kInt0  = half * 4096;          // int32 column offset
    const int cg0    = half * 64;            // global chunk base

    const int baseT = ng * 5;
    const int cntT  = ng ? 4 : 5;

    const int quad = lane >> 3;
    const int qr   = lane & 7;
    const int rb   = rg * 16;
    const int r0l  = rb + g;
    const uint32_t aoff = (uint32_t)((rb + (quad & 1) * 8 + qr) * (72 * 2)
                                     + (quad >> 1) * 16);
    uint32_t boffp[2];
#pragma unroll
    for (int p = 0; p < 2; ++p) {
        int n0 = (baseT + 2 * p) * 8;
        boffp[p] = (uint32_t)((n0 + (quad >> 1) * 8 + qr) * (72 * 2)
                              + (quad & 1) * 16);
    }
    const uint32_t boffs = (uint32_t)(((baseT + 4) * 8 + qr) * (72 * 2)
                                      + (quad & 1) * 16);

    if (tid < NSTG) mbar_init(MB0 + tid * 8, 1);
    __syncthreads();

    auto issue = [&](int c) {
        if (tid == 0) {
            const int st = c % NSTG;
            const uint32_t mb = MB0 + st * 8;
            mbar_expect_tx(mb, TXBYTES);
            tma_2d(smem0 + st * ABYTES, &tmapA, kInt0 + c * 64, row0, mb);
            bulk_g2s(B0 + st * BBYTES,
                     d_HpTc + (size_t)(cg0 + c) * B_HLV, BBYTES, mb);
        }
    };

    // smem convert: int32 TMA stage (c%3, linear 64-int rows) -> fp16 [64][72]
    auto convA = [&](int c) {
        const int4* src = (const int4*)(AIsm + (c % NSTG) * A_INTS);
        __half*     dst = Afp + (c & 1) * AF_HLV;
#pragma unroll
        for (int q = 0; q < 4; ++q) {
            int idx = q * 256 + tid;           // 1024 int4 = 64 rows x 16
            int rr = idx >> 4, c4 = idx & 15;
            int4 v = src[idx];
            uint32_t h01 = (v.x ? 0x3C00u : 0u) | (v.y ? 0x3C000000u : 0u);
            uint32_t h23 = (v.z ? 0x3C00u : 0u) | (v.w ? 0x3C000000u : 0u);
            *(uint2*)&dst[rr * 72 + c4 * 4] = make_uint2(h01, h23);
        }
    };

    issue(0);
    issue(1);

    float acc[5][4];
#pragma unroll
    for (int n = 0; n < 5; ++n)
#pragma unroll
        for (int i = 0; i < 4; ++i) acc[n][i] = 0.f;

    // prologue: chunk 0 landed -> convert -> visible
    mbar_wait(MB0 + 0, 0);
    convA(0);
    __syncthreads();

    for (int c = 0; c < 64; ++c) {
        if (c + 2 < 64) issue(c + 2);       // stage (c+2)%3 free since end of c-1

        // MMA on chunk c: A from fp16 buffer (c&1), B from stage c%3
        const uint32_t Ab = A0 + (c & 1) * (AF_HLV * 2) + aoff;
        const uint32_t Bb = B0 + (c % NSTG) * BBYTES;
#pragma unroll
        for (int ks = 0; ks < 4; ++ks) {
            uint32_t a0, a1, a2, a3;
            ldsm_x4(a0, a1, a2, a3, Ab + ks * 32);
            uint32_t b[10];
            ldsm_x4(b[0], b[1], b[2], b[3], Bb + boffp[0] + ks * 32);
            ldsm_x4(b[4], b[5], b[6], b[7], Bb + boffp[1] + ks * 32);
            if (ng == 0) ldsm_x2(b[8], b[9], Bb + boffs + ks * 32);
            mma16816(acc[0], a0, a1, a2, a3, b[0], b[1]);
            mma16816(acc[1], a0, a1, a2, a3, b[2], b[3]);
            mma16816(acc[2], a0, a1, a2, a3, b[4], b[5]);
            mma16816(acc[3], a0, a1, a2, a3, b[6], b[7]);
            if (ng == 0) mma16816(acc[4], a0, a1, a2, a3, b[8], b[9]);
        }

        if (c + 1 < 64) {
            mbar_wait(MB0 + ((c + 1) % NSTG) * 8, ((c + 1) / NSTG) & 1);
            convA(c + 1);                   // fp16 buffer (c+1)&1 — not in use
        }
        __syncthreads();                    // conv visible; stage-reuse fence
    }

    // store raw partials
    float* P = d_part + (size_t)half * N_NODES * 80;
    const int rlo = row0 + r0l;
    const int rhi = rlo + 8;
#pragma unroll
    for (int nt = 0; nt < 5; ++nt) {
        if (nt >= cntT) break;
        int gt = baseT + nt;
        int c0 = gt * 8 + 2 * t;
        *(float2*)&P[(size_t)rlo * 80 + c0] = make_float2(acc[nt][0], acc[nt][1]);
        *(float2*)&P[(size_t)rhi * 80 + c0] = make_float2(acc[nt][2], acc[nt][3]);
    }
}

// ---------------------------------------------------------------------------
// K5: combine halves: out = elu((num0+num1)/(den0+den1))
// ---------------------------------------------------------------------------
__global__ void __launch_bounds__(256)
k5_combine(float* __restrict__ out) {
    const int idx = blockIdx.x * 256 + threadIdx.x;
    const int row = idx >> 4;
    const int c0  = (idx & 15) * 4;
    const float* P0 = d_part + (size_t)row * 80;
    const float* P1 = d_part + (size_t)N_NODES * 80 + (size_t)row * 80;
    float4 n0 = *(const float4*)&P0[c0];
    float4 n1 = *(const float4*)&P1[c0];
    float den = P0[64] + P1[64];
    float inv = 1.f / den;
    float4 o;
    o.x = elu1((n0.x + n1.x) * inv);
    o.y = elu1((n0.y + n1.y) * inv);
    o.z = elu1((n0.z + n1.z) * inv);
    o.w = elu1((n0.w + n1.w) * inv);
    *(float4*)&out[(size_t)row * OUT_F + c0] = o;
}

// ---------------------------------------------------------------------------
typedef CUresult (*EncodeTiledFn)(
    CUtensorMap*, CUtensorMapDataType, cuuint32_t, void*,
    const cuuint64_t*, const cuuint64_t*, const cuuint32_t*, const cuuint32_t*,
    CUtensorMapInterleave, CUtensorMapSwizzle, CUtensorMapL2promotion,
    CUtensorMapFloatOOBfill);

extern "C" void kernel_launch(void* const* d_in, const int* in_sizes, int n_in,
                              void* d_out, int out_size) {
    const float* X    = (const float*)d_in[0];
    const int*   adj  = (const int*)  d_in[1];
    const float* W    = (const float*)d_in[2];
    const float* avec = (const float*)d_in[3];
    float* out = (float*)d_out;

    // Build the adjacency tensor map (pure host work; capture-safe)
    EncodeTiledFn enc = nullptr;
    cudaDriverEntryPointQueryResult qres;
    cudaGetDriverEntryPointByVersion("cuTensorMapEncodeTiled", (void**)&enc,
                                     12000, cudaEnableDefault, &qres);
    CUtensorMap tmapA;
    cuuint64_t dims[2]    = {N_NODES, N_NODES};       // {ints per row, rows}
    cuuint64_t strides[1] = {(cuuint64_t)N_NODES * 4};
    cuuint32_t box[2]     = {64, 64};                 // 64 ints x 64 rows
    cuuint32_t es[2]      = {1, 1};
    enc(&tmapA, CU_TENSOR_MAP_DATA_TYPE_UINT32, 2, (void*)adj,
        dims, strides, box, es,
        CU_TENSOR_MAP_INTERLEAVE_NONE, CU_TENSOR_MAP_SWIZZLE_NONE,
        CU_TENSOR_MAP_L2_PROMOTION_L2_128B, CU_TENSOR_MAP_FLOAT_OOB_FILL_NONE);

    cudaFuncSetAttribute(k1_mma, cudaFuncAttributeMaxDynamicSharedMemorySize, K1_SMEM);
    cudaFuncSetAttribute(k4_split, cudaFuncAttributeMaxDynamicSharedMemorySize, K4_SMEM);

    k1_mma<<<128, 128, K1_SMEM>>>(X, W, avec);
    k3_build<<<64, 128>>>();
    k4_split<<<256, 256, K4_SMEM>>>(tmapA);
    k5_combine<<<N_NODES * OUT_F / 1024, 256>>>(out);
}